// round 12
// baseline (speedup 1.0000x reference)
#include <cuda_runtime.h>
#include <cuda_bf16.h>
#include <cstdint>

// Problem constants
#define BB 32
#define SS 512
#define HH 768
#define TT 100
#define THH 512
#define LL 5

// Scratch (static device globals — no allocation)
__device__ float g_scratch[BB * SS * HH];   // GEMM1 output: 50.3 MB
__device__ float g_rbar[BB * HH];
__device__ float g_msum[BB];
__device__ float g_comb[BB * (HH + TT)];
__device__ float g_fused[BB * THH];
__device__ __align__(16) __nv_bfloat16 g_w1t_hi[LL * HH * HH];  // W1^T hi, [L][N][K]
__device__ __align__(16) __nv_bfloat16 g_w1t_lo[LL * HH * HH];  // W1^T lo
__device__ __align__(16) __nv_bfloat16 g_a_hi[BB * SS * HH];    // seq hi, [M][K]
__device__ __align__(16) __nv_bfloat16 g_a_lo[BB * SS * HH];    // seq lo

// ---------------------------------------------------------------------------
// mma.sync m16n8k16 bf16 + ldmatrix + cp.async (legacy, base-sm_100-legal)
// ---------------------------------------------------------------------------
__device__ __forceinline__ void mma_bf16(float* c, const uint32_t* a, const uint32_t* b) {
    asm volatile(
        "mma.sync.aligned.m16n8k16.row.col.f32.bf16.bf16.f32 "
        "{%0,%1,%2,%3}, {%4,%5,%6,%7}, {%8,%9}, {%0,%1,%2,%3};"
        : "+f"(c[0]), "+f"(c[1]), "+f"(c[2]), "+f"(c[3])
        : "r"(a[0]), "r"(a[1]), "r"(a[2]), "r"(a[3]), "r"(b[0]), "r"(b[1]));
}
__device__ __forceinline__ void ldsm_x4(uint32_t* r, uint32_t saddr) {
    asm volatile(
        "ldmatrix.sync.aligned.m8n8.x4.shared.b16 {%0,%1,%2,%3}, [%4];"
        : "=r"(r[0]), "=r"(r[1]), "=r"(r[2]), "=r"(r[3]) : "r"(saddr));
}
__device__ __forceinline__ uint32_t smem_u32(const void* p) {
    uint32_t a;
    asm("{ .reg .u64 t; cvta.to.shared.u64 t, %1; cvt.u32.u64 %0, t; }"
        : "=r"(a) : "l"(p));
    return a;
}
__device__ __forceinline__ void cp_async16(uint32_t dst, const void* src) {
    asm volatile("cp.async.cg.shared.global [%0], [%1], 16;"
                 :: "r"(dst), "l"(src));
}
#define CP_COMMIT() asm volatile("cp.async.commit_group;")
#define CP_WAIT2()  asm volatile("cp.async.wait_group 2;")

// ===========================================================================
// Kernel: init — zero rbar, mask sums, seed comb (bias+lda) and fused (bf)
// ===========================================================================
__global__ __launch_bounds__(256) void init_kernel(
    const float* __restrict__ mask, const int* __restrict__ lang,
    const float* __restrict__ b2, const float* __restrict__ lda,
    const float* __restrict__ bf)
{
    const int b = blockIdx.x;
    const int tid = threadIdx.x;
    const int lane = tid & 31;
    const int warp = tid >> 5;
    __shared__ float red[8];
    __shared__ float sh_m;

    for (int c = tid; c < HH; c += 256) g_rbar[b * HH + c] = 0.0f;

    float ms = 0.0f;
    for (int s = tid; s < SS; s += 256) ms += mask[b * SS + s];
#pragma unroll
    for (int o = 16; o > 0; o >>= 1) ms += __shfl_xor_sync(0xffffffffu, ms, o);
    if (lane == 0) red[warp] = ms;
    __syncthreads();
    if (tid == 0) {
        float v = 0.0f;
#pragma unroll
        for (int i = 0; i < 8; i++) v += red[i];
        g_msum[b] = v;
        sh_m = v;
    }
    __syncthreads();

    const int l = lang[b];
    const float Mtot = sh_m;
    const float invD = 1.0f / (Mtot + 1e-10f);
    for (int n = tid; n < HH; n += 256)
        g_comb[b * (HH + TT) + n] = Mtot * b2[l * HH + n] * invD;
    for (int i = tid; i < TT; i += 256)
        g_comb[b * (HH + TT) + HH + i] = lda[b * TT + i];
    for (int n = tid; n < THH; n += 256)
        g_fused[b * THH + n] = bf[n];
}

// ===========================================================================
// Kernel: split seq -> bf16 hi/lo. grid 12288, block 256, 1 float4/thread.
// ===========================================================================
__global__ __launch_bounds__(256) void a_prep_kernel(const float* __restrict__ seq)
{
    const int i = blockIdx.x * 256 + threadIdx.x;   // float4 index
    float4 v = *reinterpret_cast<const float4*>(seq + (size_t)i * 4);
    const float x[4] = {v.x, v.y, v.z, v.w};
    uint32_t h[2], lo[2];
#pragma unroll
    for (int j = 0; j < 2; j++) {
        __nv_bfloat16 h0 = __float2bfloat16(x[2 * j]);
        __nv_bfloat16 h1 = __float2bfloat16(x[2 * j + 1]);
        __nv_bfloat16 l0 = __float2bfloat16(x[2 * j] - __bfloat162float(h0));
        __nv_bfloat16 l1 = __float2bfloat16(x[2 * j + 1] - __bfloat162float(h1));
        h[j]  = ((uint32_t)__bfloat16_as_ushort(h1) << 16) | __bfloat16_as_ushort(h0);
        lo[j] = ((uint32_t)__bfloat16_as_ushort(l1) << 16) | __bfloat16_as_ushort(l0);
    }
    *reinterpret_cast<uint2*>(g_a_hi + (size_t)i * 4) = make_uint2(h[0], h[1]);
    *reinterpret_cast<uint2*>(g_a_lo + (size_t)i * 4) = make_uint2(lo[0], lo[1]);
}

// ===========================================================================
// Kernel: W1 -> W1^T split to bf16 hi/lo. grid (24,24,L), block (32,8)
// ===========================================================================
__global__ __launch_bounds__(256) void w1t_prep_kernel(const float* __restrict__ W1)
{
    __shared__ float tile[32][33];
    const int l = blockIdx.z;
    const int n0 = blockIdx.x * 32;
    const int k0 = blockIdx.y * 32;
    const float* __restrict__ W = W1 + (size_t)l * HH * HH;
#pragma unroll
    for (int j = 0; j < 4; j++) {
        int k = k0 + threadIdx.y + j * 8;
        tile[threadIdx.y + j * 8][threadIdx.x] = W[(size_t)k * HH + n0 + threadIdx.x];
    }
    __syncthreads();
#pragma unroll
    for (int j = 0; j < 4; j++) {
        int n = n0 + threadIdx.y + j * 8;
        float v = tile[threadIdx.x][threadIdx.y + j * 8];
        __nv_bfloat16 h = __float2bfloat16(v);
        __nv_bfloat16 lo = __float2bfloat16(v - __bfloat162float(h));
        size_t o = (size_t)l * HH * HH + (size_t)n * HH + k0 + threadIdx.x;
        g_w1t_hi[o] = h;
        g_w1t_lo[o] = lo;
    }
}

// ===========================================================================
// Kernel: GEMM1 via mma.sync bf16-split + ldmatrix + 4-stage cp.async pipeline.
// CTA tile 128x128, BK=32, 8 warps (2m x 4n), warp tile 64x32.
// Smem: 4 stages x 4 tiles x (128 rows x 80B) = 160KB dynamic. 1 CTA/SM.
// One __syncthreads per chunk; refill issued right after the sync, so the
// compute phase overlaps the loads for chunk it+3.
// ===========================================================================
#define TILE_BYTES 10240  // 128 * 80
#define STAGE_BYTES 40960
#define NSTAGE 4
#define NCH (HH / 32)     // 24

__global__ __launch_bounds__(256) void gemm1_mma_kernel(
    const int* __restrict__ lang,
    const float* __restrict__ b1)
{
    extern __shared__ char smem[];
    const uint32_t sbase = smem_u32(smem);

    const int tid = threadIdx.x;
    const int wid = tid >> 5;
    const int lane = tid & 31;
    const int g = lane >> 2;
    const int tg = lane & 3;

    const int n0 = blockIdx.x * 128;
    const int m0 = blockIdx.y * 128;
    const int b = m0 / SS;
    const int l = lang[b];

    const int wm = (wid & 1) * 64;
    const int wn = (wid >> 1) * 32;

    // ldmatrix per-lane source coords
    const int a_r = (lane & 7) + 8 * ((lane >> 3) & 1);
    const int a_c = 8 * (lane >> 4);
    const int b_r = (lane & 7) + 8 * (lane >> 4);
    const int b_c = 8 * ((lane >> 3) & 1);

    const __nv_bfloat16* __restrict__ Ah = g_a_hi + (size_t)m0 * HH;
    const __nv_bfloat16* __restrict__ Al = g_a_lo + (size_t)m0 * HH;
    const __nv_bfloat16* __restrict__ Bh = g_w1t_hi + (size_t)l * HH * HH + (size_t)n0 * HH;
    const __nv_bfloat16* __restrict__ Bl = g_w1t_lo + (size_t)l * HH * HH + (size_t)n0 * HH;

    // cp.async coords: per tile, 512 x 16B chunks; 2 per thread.
    const int ld_row0 = tid >> 2;              // rows 0..63
    const int ld_row1 = 64 + (tid >> 2);       // rows 64..127
    const int ld_c = (tid & 3) * 8;            // bf16 elem offset (16B chunk)

    float acc[4][4][4];
#pragma unroll
    for (int mi = 0; mi < 4; mi++)
#pragma unroll
        for (int ni = 0; ni < 4; ni++)
#pragma unroll
            for (int r = 0; r < 4; r++) acc[mi][ni][r] = 0.0f;

#define ISSUE_CHUNK(ST, K0)                                                     \
    do {                                                                        \
        const uint32_t sb_ = sbase + (ST) * STAGE_BYTES;                        \
        cp_async16(sb_ + 0 * TILE_BYTES + ld_row0 * 80 + ld_c * 2,              \
                   Ah + (size_t)ld_row0 * HH + (K0) + ld_c);                    \
        cp_async16(sb_ + 0 * TILE_BYTES + ld_row1 * 80 + ld_c * 2,              \
                   Ah + (size_t)ld_row1 * HH + (K0) + ld_c);                    \
        cp_async16(sb_ + 1 * TILE_BYTES + ld_row0 * 80 + ld_c * 2,              \
                   Al + (size_t)ld_row0 * HH + (K0) + ld_c);                    \
        cp_async16(sb_ + 1 * TILE_BYTES + ld_row1 * 80 + ld_c * 2,              \
                   Al + (size_t)ld_row1 * HH + (K0) + ld_c);                    \
        cp_async16(sb_ + 2 * TILE_BYTES + ld_row0 * 80 + ld_c * 2,              \
                   Bh + (size_t)ld_row0 * HH + (K0) + ld_c);                    \
        cp_async16(sb_ + 2 * TILE_BYTES + ld_row1 * 80 + ld_c * 2,              \
                   Bh + (size_t)ld_row1 * HH + (K0) + ld_c);                    \
        cp_async16(sb_ + 3 * TILE_BYTES + ld_row0 * 80 + ld_c * 2,              \
                   Bl + (size_t)ld_row0 * HH + (K0) + ld_c);                    \
        cp_async16(sb_ + 3 * TILE_BYTES + ld_row1 * 80 + ld_c * 2,              \
                   Bl + (size_t)ld_row1 * HH + (K0) + ld_c);                    \
    } while (0)

    // ---- prologue: fill stages 0..2 ----
    ISSUE_CHUNK(0, 0);
    CP_COMMIT();
    ISSUE_CHUNK(1, 32);
    CP_COMMIT();
    ISSUE_CHUNK(2, 64);
    CP_COMMIT();

    for (int it = 0; it < NCH; ++it) {
        const int st = it & 3;
        const uint32_t as_hi = sbase + st * STAGE_BYTES;
        const uint32_t as_lo = as_hi + TILE_BYTES;
        const uint32_t bs_hi = as_hi + 2 * TILE_BYTES;
        const uint32_t bs_lo = as_hi + 3 * TILE_BYTES;

        // chunk it is guaranteed landed when ≤2 newer groups remain in flight
        CP_WAIT2();
        __syncthreads();

        // refill the stage freed by iteration it-1; overlaps with compute below
        if (it + 3 < NCH)
            ISSUE_CHUNK((it + 3) & 3, (it + 3) * 32);
        CP_COMMIT();

        // ---- compute: 2 k16 steps, ldmatrix-fed ----
#pragma unroll
        for (int ks = 0; ks < 2; ks++) {
            const int kk = ks * 16;

            uint32_t bh[2][4], bl[2][4];
#pragma unroll
            for (int p = 0; p < 2; p++) {
                uint32_t off = (uint32_t)((wn + p * 16 + b_r) * 80 + (kk + b_c) * 2);
                ldsm_x4(bh[p], bs_hi + off);
                ldsm_x4(bl[p], bs_lo + off);
            }

            uint32_t ah[4][4];
#pragma unroll
            for (int mi = 0; mi < 4; mi++) {
                uint32_t off = (uint32_t)((wm + mi * 16 + a_r) * 80 + (kk + a_c) * 2);
                ldsm_x4(ah[mi], as_hi + off);
            }
#pragma unroll
            for (int mi = 0; mi < 4; mi++) {
#pragma unroll
                for (int ni = 0; ni < 4; ni++) {
                    mma_bf16(acc[mi][ni], ah[mi], &bh[ni >> 1][(ni & 1) * 2]);
                    mma_bf16(acc[mi][ni], ah[mi], &bl[ni >> 1][(ni & 1) * 2]);
                }
            }
#pragma unroll
            for (int mi = 0; mi < 4; mi++) {
                uint32_t al4[4];
                uint32_t off = (uint32_t)((wm + mi * 16 + a_r) * 80 + (kk + a_c) * 2);
                ldsm_x4(al4, as_lo + off);
#pragma unroll
                for (int ni = 0; ni < 4; ni++)
                    mma_bf16(acc[mi][ni], al4, &bh[ni >> 1][(ni & 1) * 2]);
            }
        }
        // no second sync: next iteration's top sync protects stage reuse
    }
#undef ISSUE_CHUNK

    // ---- epilogue: add bias, write to g_scratch ----
    const float* __restrict__ bp = b1 + (size_t)l * HH;
#pragma unroll
    for (int ni = 0; ni < 4; ni++) {
        int n = n0 + wn + ni * 8 + tg * 2;
        float2 bv = *reinterpret_cast<const float2*>(bp + n);
#pragma unroll
        for (int mi = 0; mi < 4; mi++) {
            int mA = m0 + wm + mi * 16 + g;
            float2 o0, o1;
            o0.x = acc[mi][ni][0] + bv.x;
            o0.y = acc[mi][ni][1] + bv.y;
            o1.x = acc[mi][ni][2] + bv.x;
            o1.y = acc[mi][ni][3] + bv.y;
            *reinterpret_cast<float2*>(g_scratch + (size_t)mA * HH + n) = o0;
            *reinterpret_cast<float2*>(g_scratch + (size_t)(mA + 8) * HH + n) = o1;
        }
    }
}

// ===========================================================================
// Kernel: LN + ReLU + masked pool
// ===========================================================================
__global__ __launch_bounds__(256) void ln_relu_pool_kernel(
    const float* __restrict__ mask,
    const int* __restrict__ lang,
    const float* __restrict__ g1,
    const float* __restrict__ be1)
{
    __shared__ float accum[HH];
    const int blk = blockIdx.x;
    const int b = blk >> 3;
    const int s_base = (blk & 7) * 64;
    const int tid = threadIdx.x;
    const int w = tid >> 5;
    const int lane = tid & 31;

    for (int c = tid; c < HH; c += 256) accum[c] = 0.0f;
    __syncthreads();

    const int l = lang[b];
    const float* __restrict__ g = g1 + (size_t)l * HH;
    const float* __restrict__ be = be1 + (size_t)l * HH;

    float gv[24], bev[24];
#pragma unroll
    for (int i = 0; i < 6; i++) {
        float4 gg = *reinterpret_cast<const float4*>(g + i * 128 + lane * 4);
        float4 bb = *reinterpret_cast<const float4*>(be + i * 128 + lane * 4);
        gv[i * 4 + 0] = gg.x; gv[i * 4 + 1] = gg.y;
        gv[i * 4 + 2] = gg.z; gv[i * 4 + 3] = gg.w;
        bev[i * 4 + 0] = bb.x; bev[i * 4 + 1] = bb.y;
        bev[i * 4 + 2] = bb.z; bev[i * 4 + 3] = bb.w;
    }

    float racc[24];
#pragma unroll
    for (int i = 0; i < 24; i++) racc[i] = 0.0f;

    for (int r = 0; r < 8; r++) {
        const int s = s_base + w * 8 + r;
        const float* __restrict__ row = g_scratch + ((size_t)b * SS + s) * HH;

        float x[24];
        float sum = 0.0f, sq = 0.0f;
#pragma unroll
        for (int i = 0; i < 6; i++) {
            float4 v = *reinterpret_cast<const float4*>(row + i * 128 + lane * 4);
            x[i * 4 + 0] = v.x; x[i * 4 + 1] = v.y;
            x[i * 4 + 2] = v.z; x[i * 4 + 3] = v.w;
            sum += v.x + v.y + v.z + v.w;
            sq += v.x * v.x + v.y * v.y + v.z * v.z + v.w * v.w;
        }
#pragma unroll
        for (int o = 16; o > 0; o >>= 1) {
            sum += __shfl_xor_sync(0xffffffffu, sum, o);
            sq  += __shfl_xor_sync(0xffffffffu, sq, o);
        }
        const float mean = sum * (1.0f / HH);
        const float var = sq * (1.0f / HH) - mean * mean;
        const float rstd = rsqrtf(var + 1e-5f);
        const float mk = mask[b * SS + s];

#pragma unroll
        for (int i = 0; i < 24; i++) {
            float v = (x[i] - mean) * rstd * gv[i] + bev[i];
            racc[i] += fmaxf(v, 0.0f) * mk;
        }
    }

#pragma unroll
    for (int i = 0; i < 6; i++) {
#pragma unroll
        for (int j = 0; j < 4; j++) {
            int c = i * 128 + lane * 4 + j;
            atomicAdd(&accum[c], racc[i * 4 + j]);
        }
    }
    __syncthreads();
    for (int c = tid; c < HH; c += 256)
        atomicAdd(&g_rbar[b * HH + c], accum[c]);
}

// ===========================================================================
// Kernel: gemv2 split-K x8. grid (3, BB, 8). Partial dot into g_comb (atomic).
// ===========================================================================
__global__ __launch_bounds__(256) void gemv2_kernel(
    const int* __restrict__ lang,
    const float* __restrict__ W2)
{
    const int b = blockIdx.y;
    const int z = blockIdx.z;
    const int n = blockIdx.x * 256 + threadIdx.x;
    const int tid = threadIdx.x;
    const int kb = z * 96;
    __shared__ float tvec[96];

    if (tid < 96) tvec[tid] = g_rbar[b * HH + kb + tid];
    __syncthreads();

    const int l = lang[b];
    const float invD = 1.0f / (g_msum[b] + 1e-10f);
    const float* __restrict__ W2l = W2 + (size_t)l * HH * HH + (size_t)kb * HH;

    float acc = 0.0f;
#pragma unroll 8
    for (int h = 0; h < 96; h++)
        acc += tvec[h] * W2l[(size_t)h * HH + n];

    atomicAdd(&g_comb[b * (HH + TT) + n], acc * invD);
}

// ===========================================================================
// Kernel: fuse split-K x7. grid (2, BB, 7). 868 = 7*124.
// ===========================================================================
__global__ __launch_bounds__(256) void fuse_kernel(const float* __restrict__ Wf)
{
    const int b = blockIdx.y;
    const int z = blockIdx.z;
    const int n = blockIdx.x * 256 + threadIdx.x;
    const int tid = threadIdx.x;
    const int ib = z * 124;
    __shared__ float comb[124];

    if (tid < 124) comb[tid] = g_comb[b * (HH + TT) + ib + tid];
    __syncthreads();

    float f = 0.0f;
#pragma unroll 4
    for (int i = 0; i < 124; i++)
        f += comb[i] * Wf[(size_t)(ib + i) * THH + n];

    atomicAdd(&g_fused[b * THH + n], f);
}

// ===========================================================================
// Kernel: final LN + relu. grid BB, block 512.
// ===========================================================================
__global__ __launch_bounds__(512) void final_ln_kernel(
    const float* __restrict__ gf,
    const float* __restrict__ bef,
    float* __restrict__ out)
{
    const int b = blockIdx.x;
    const int tid = threadIdx.x;
    const int lane = tid & 31;
    const int warp = tid >> 5;
    __shared__ float red[32];

    const float f = g_fused[b * THH + tid];

    float sum = f, sq = f * f;
#pragma unroll
    for (int o = 16; o > 0; o >>= 1) {
        sum += __shfl_xor_sync(0xffffffffu, sum, o);
        sq  += __shfl_xor_sync(0xffffffffu, sq, o);
    }
    if (lane == 0) { red[warp] = sum; red[warp + 16] = sq; }
    __syncthreads();
    if (tid < 32) {
        float v = (tid < 16) ? red[tid] : 0.0f;
        float v2 = (tid < 16) ? red[tid + 16] : 0.0f;
#pragma unroll
        for (int o = 8; o > 0; o >>= 1) {
            v  += __shfl_xor_sync(0xffffffffu, v, o);
            v2 += __shfl_xor_sync(0xffffffffu, v2, o);
        }
        if (tid == 0) { red[0] = v; red[1] = v2; }
    }
    __syncthreads();
    const float mean = red[0] * (1.0f / THH);
    const float var = red[1] * (1.0f / THH) - mean * mean;
    const float rstd = rsqrtf(var + 1e-5f);

    float o = (f - mean) * rstd * gf[tid] + bef[tid];
    out[b * THH + tid] = fmaxf(o, 0.0f);
}

// ===========================================================================
extern "C" void kernel_launch(void* const* d_in, const int* in_sizes, int n_in,
                              void* d_out, int out_size)
{
    const float* seq  = (const float*)d_in[0];
    const float* mask = (const float*)d_in[1];
    const int*   lang = (const int*)d_in[2];
    const float* lda  = (const float*)d_in[3];
    const float* W1   = (const float*)d_in[4];
    const float* b1   = (const float*)d_in[5];
    const float* g1   = (const float*)d_in[6];
    const float* be1  = (const float*)d_in[7];
    const float* W2   = (const float*)d_in[8];
    const float* b2   = (const float*)d_in[9];
    const float* Wf   = (const float*)d_in[10];
    const float* bf   = (const float*)d_in[11];
    const float* gf   = (const float*)d_in[12];
    const float* bef  = (const float*)d_in[13];
    float* out = (float*)d_out;

    (void)in_sizes; (void)n_in; (void)out_size;

    cudaFuncSetAttribute(gemm1_mma_kernel,
                         cudaFuncAttributeMaxDynamicSharedMemorySize,
                         NSTAGE * STAGE_BYTES);

    init_kernel<<<BB, 256>>>(mask, lang, b2, lda, bf);
    a_prep_kernel<<<(BB * SS * HH) / 1024, 256>>>(seq);
    w1t_prep_kernel<<<dim3(HH / 32, HH / 32, LL), dim3(32, 8)>>>(W1);
    gemm1_mma_kernel<<<dim3(HH / 128, (BB * SS) / 128), 256,
                      NSTAGE * STAGE_BYTES>>>(lang, b1);
    ln_relu_pool_kernel<<<BB * 8, 256>>>(mask, lang, g1, be1);
    gemv2_kernel<<<dim3(3, BB, 8), 256>>>(lang, W2);
    fuse_kernel<<<dim3(2, BB, 7), 256>>>(Wf);
    final_ln_kernel<<<BB, 512>>>(gf, bef, out);
}

// round 13
// speedup vs baseline: 1.1952x; 1.1952x over previous
#include <cuda_runtime.h>
#include <cuda_bf16.h>
#include <cstdint>

// Problem constants
#define BB 32
#define SS 512
#define HH 768
#define TT 100
#define THH 512
#define LL 5

// Scratch (static device globals — no allocation)
__device__ float g_scratch[BB * SS * HH];   // GEMM1 output: 50.3 MB
__device__ float g_rbar[BB * HH];
__device__ float g_msum[BB];
__device__ float g_comb[BB * (HH + TT)];
__device__ float g_fused[BB * THH];
__device__ __align__(16) __nv_bfloat16 g_w1t_hi[LL * HH * HH];  // W1^T hi, [L][N][K]
__device__ __align__(16) __nv_bfloat16 g_w1t_lo[LL * HH * HH];  // W1^T lo
__device__ __align__(16) __nv_bfloat16 g_a_hi[BB * SS * HH];    // seq hi, [M][K]
__device__ __align__(16) __nv_bfloat16 g_a_lo[BB * SS * HH];    // seq lo

// ---------------------------------------------------------------------------
// mma.sync m16n8k16 bf16 + ldmatrix + cp.async (legacy, base-sm_100-legal)
// ---------------------------------------------------------------------------
__device__ __forceinline__ void mma_bf16(float* c, const uint32_t* a, const uint32_t* b) {
    asm volatile(
        "mma.sync.aligned.m16n8k16.row.col.f32.bf16.bf16.f32 "
        "{%0,%1,%2,%3}, {%4,%5,%6,%7}, {%8,%9}, {%0,%1,%2,%3};"
        : "+f"(c[0]), "+f"(c[1]), "+f"(c[2]), "+f"(c[3])
        : "r"(a[0]), "r"(a[1]), "r"(a[2]), "r"(a[3]), "r"(b[0]), "r"(b[1]));
}
__device__ __forceinline__ void ldsm_x4(uint32_t* r, uint32_t saddr) {
    asm volatile(
        "ldmatrix.sync.aligned.m8n8.x4.shared.b16 {%0,%1,%2,%3}, [%4];"
        : "=r"(r[0]), "=r"(r[1]), "=r"(r[2]), "=r"(r[3]) : "r"(saddr));
}
__device__ __forceinline__ uint32_t smem_u32(const void* p) {
    uint32_t a;
    asm("{ .reg .u64 t; cvta.to.shared.u64 t, %1; cvt.u32.u64 %0, t; }"
        : "=r"(a) : "l"(p));
    return a;
}
__device__ __forceinline__ void cp_async16(uint32_t dst, const void* src) {
    asm volatile("cp.async.cg.shared.global [%0], [%1], 16;"
                 :: "r"(dst), "l"(src));
}
#define CP_COMMIT() asm volatile("cp.async.commit_group;")
#define CP_WAIT1()  asm volatile("cp.async.wait_group 1;")

// Swizzled byte offset within a 128x64B tile: row, chunk c (16B units, 0..3)
#define SWZ_OFF(row, c) ((uint32_t)((row) * 64 + (((c) ^ (((row) >> 1) & 3)) << 4)))

// ===========================================================================
// Kernel: init — zero rbar, mask sums, seed comb (bias+lda) and fused (bf)
// ===========================================================================
__global__ __launch_bounds__(256) void init_kernel(
    const float* __restrict__ mask, const int* __restrict__ lang,
    const float* __restrict__ b2, const float* __restrict__ lda,
    const float* __restrict__ bf)
{
    const int b = blockIdx.x;
    const int tid = threadIdx.x;
    const int lane = tid & 31;
    const int warp = tid >> 5;
    __shared__ float red[8];
    __shared__ float sh_m;

    for (int c = tid; c < HH; c += 256) g_rbar[b * HH + c] = 0.0f;

    float ms = 0.0f;
    for (int s = tid; s < SS; s += 256) ms += mask[b * SS + s];
#pragma unroll
    for (int o = 16; o > 0; o >>= 1) ms += __shfl_xor_sync(0xffffffffu, ms, o);
    if (lane == 0) red[warp] = ms;
    __syncthreads();
    if (tid == 0) {
        float v = 0.0f;
#pragma unroll
        for (int i = 0; i < 8; i++) v += red[i];
        g_msum[b] = v;
        sh_m = v;
    }
    __syncthreads();

    const int l = lang[b];
    const float Mtot = sh_m;
    const float invD = 1.0f / (Mtot + 1e-10f);
    for (int n = tid; n < HH; n += 256)
        g_comb[b * (HH + TT) + n] = Mtot * b2[l * HH + n] * invD;
    for (int i = tid; i < TT; i += 256)
        g_comb[b * (HH + TT) + HH + i] = lda[b * TT + i];
    for (int n = tid; n < THH; n += 256)
        g_fused[b * THH + n] = bf[n];
}

// ===========================================================================
// Kernel: split seq -> bf16 hi/lo. grid 12288, block 256, 1 float4/thread.
// ===========================================================================
__global__ __launch_bounds__(256) void a_prep_kernel(const float* __restrict__ seq)
{
    const int i = blockIdx.x * 256 + threadIdx.x;   // float4 index
    float4 v = *reinterpret_cast<const float4*>(seq + (size_t)i * 4);
    const float x[4] = {v.x, v.y, v.z, v.w};
    uint32_t h[2], lo[2];
#pragma unroll
    for (int j = 0; j < 2; j++) {
        __nv_bfloat16 h0 = __float2bfloat16(x[2 * j]);
        __nv_bfloat16 h1 = __float2bfloat16(x[2 * j + 1]);
        __nv_bfloat16 l0 = __float2bfloat16(x[2 * j] - __bfloat162float(h0));
        __nv_bfloat16 l1 = __float2bfloat16(x[2 * j + 1] - __bfloat162float(h1));
        h[j]  = ((uint32_t)__bfloat16_as_ushort(h1) << 16) | __bfloat16_as_ushort(h0);
        lo[j] = ((uint32_t)__bfloat16_as_ushort(l1) << 16) | __bfloat16_as_ushort(l0);
    }
    *reinterpret_cast<uint2*>(g_a_hi + (size_t)i * 4) = make_uint2(h[0], h[1]);
    *reinterpret_cast<uint2*>(g_a_lo + (size_t)i * 4) = make_uint2(lo[0], lo[1]);
}

// ===========================================================================
// Kernel: W1 -> W1^T split to bf16 hi/lo. grid (24,24,L), block (32,8)
// ===========================================================================
__global__ __launch_bounds__(256) void w1t_prep_kernel(const float* __restrict__ W1)
{
    __shared__ float tile[32][33];
    const int l = blockIdx.z;
    const int n0 = blockIdx.x * 32;
    const int k0 = blockIdx.y * 32;
    const float* __restrict__ W = W1 + (size_t)l * HH * HH;
#pragma unroll
    for (int j = 0; j < 4; j++) {
        int k = k0 + threadIdx.y + j * 8;
        tile[threadIdx.y + j * 8][threadIdx.x] = W[(size_t)k * HH + n0 + threadIdx.x];
    }
    __syncthreads();
#pragma unroll
    for (int j = 0; j < 4; j++) {
        int n = n0 + threadIdx.y + j * 8;
        float v = tile[threadIdx.x][threadIdx.y + j * 8];
        __nv_bfloat16 h = __float2bfloat16(v);
        __nv_bfloat16 lo = __float2bfloat16(v - __bfloat162float(h));
        size_t o = (size_t)l * HH * HH + (size_t)n * HH + k0 + threadIdx.x;
        g_w1t_hi[o] = h;
        g_w1t_lo[o] = lo;
    }
}

// ===========================================================================
// Kernel: GEMM1 via mma.sync bf16-split + ldmatrix + 3-stage cp.async pipeline.
// CTA tile 128x128, BK=32, 8 warps (2m x 4n), warp tile 64x32.
// Swizzled 64B rows -> tile 8KB, stage 32KB, 3 stages = 96KB/CTA, 2 CTA/SM.
// One __syncthreads per chunk; refill issued before compute (ahead-by-2).
// ===========================================================================
#define TILE_BYTES 8192   // 128 * 64
#define STAGE_BYTES 32768
#define NSTAGE 3
#define NCH (HH / 32)     // 24

__global__ void __launch_bounds__(256, 2) gemm1_mma_kernel(
    const int* __restrict__ lang,
    const float* __restrict__ b1)
{
    extern __shared__ char smem[];
    const uint32_t sbase = smem_u32(smem);

    const int tid = threadIdx.x;
    const int wid = tid >> 5;
    const int lane = tid & 31;
    const int g = lane >> 2;
    const int tg = lane & 3;

    const int n0 = blockIdx.x * 128;
    const int m0 = blockIdx.y * 128;
    const int b = m0 / SS;
    const int l = lang[b];

    const int wm = (wid & 1) * 64;
    const int wn = (wid >> 1) * 32;

    // ldmatrix per-lane source coords
    const int a_r = (lane & 7) + 8 * ((lane >> 3) & 1);
    const int a_c = 8 * (lane >> 4);             // elem offset: 0 or 8
    const int b_r = (lane & 7) + 8 * (lane >> 4);
    const int b_c = 8 * ((lane >> 3) & 1);

    const __nv_bfloat16* __restrict__ Ah = g_a_hi + (size_t)m0 * HH;
    const __nv_bfloat16* __restrict__ Al = g_a_lo + (size_t)m0 * HH;
    const __nv_bfloat16* __restrict__ Bh = g_w1t_hi + (size_t)l * HH * HH + (size_t)n0 * HH;
    const __nv_bfloat16* __restrict__ Bl = g_w1t_lo + (size_t)l * HH * HH + (size_t)n0 * HH;

    // cp.async coords: per tile, 512 x 16B chunks; 2 per thread.
    const int ld_row0 = tid >> 2;              // rows 0..63
    const int ld_row1 = 64 + (tid >> 2);       // rows 64..127
    const int ld_ch = tid & 3;                 // 16B chunk index 0..3
    const uint32_t sw_off0 = SWZ_OFF(ld_row0, ld_ch);
    const uint32_t sw_off1 = SWZ_OFF(ld_row1, ld_ch);
    const int ld_e = ld_ch * 8;                // source elem offset

    float acc[4][4][4];
#pragma unroll
    for (int mi = 0; mi < 4; mi++)
#pragma unroll
        for (int ni = 0; ni < 4; ni++)
#pragma unroll
            for (int r = 0; r < 4; r++) acc[mi][ni][r] = 0.0f;

#define ISSUE_CHUNK(ST, K0)                                                     \
    do {                                                                        \
        const uint32_t sb_ = sbase + (ST) * STAGE_BYTES;                        \
        cp_async16(sb_ + 0 * TILE_BYTES + sw_off0,                              \
                   Ah + (size_t)ld_row0 * HH + (K0) + ld_e);                    \
        cp_async16(sb_ + 0 * TILE_BYTES + sw_off1,                              \
                   Ah + (size_t)ld_row1 * HH + (K0) + ld_e);                    \
        cp_async16(sb_ + 1 * TILE_BYTES + sw_off0,                              \
                   Al + (size_t)ld_row0 * HH + (K0) + ld_e);                    \
        cp_async16(sb_ + 1 * TILE_BYTES + sw_off1,                              \
                   Al + (size_t)ld_row1 * HH + (K0) + ld_e);                    \
        cp_async16(sb_ + 2 * TILE_BYTES + sw_off0,                              \
                   Bh + (size_t)ld_row0 * HH + (K0) + ld_e);                    \
        cp_async16(sb_ + 2 * TILE_BYTES + sw_off1,                              \
                   Bh + (size_t)ld_row1 * HH + (K0) + ld_e);                    \
        cp_async16(sb_ + 3 * TILE_BYTES + sw_off0,                              \
                   Bl + (size_t)ld_row0 * HH + (K0) + ld_e);                    \
        cp_async16(sb_ + 3 * TILE_BYTES + sw_off1,                              \
                   Bl + (size_t)ld_row1 * HH + (K0) + ld_e);                    \
    } while (0)

    // ---- prologue: fill stages 0 and 1 ----
    ISSUE_CHUNK(0, 0);
    CP_COMMIT();
    ISSUE_CHUNK(1, 32);
    CP_COMMIT();

    int stage = 0;
    for (int it = 0; it < NCH; ++it) {
        const int st = stage;                  // it % 3
        stage = (stage == 2) ? 0 : stage + 1;
        const uint32_t as_hi = sbase + st * STAGE_BYTES;
        const uint32_t as_lo = as_hi + TILE_BYTES;
        const uint32_t bs_hi = as_hi + 2 * TILE_BYTES;
        const uint32_t bs_lo = as_hi + 3 * TILE_BYTES;

        // chunk it landed when ≤1 newer group remains in flight
        CP_WAIT1();
        __syncthreads();

        // refill the stage freed by iteration it-1; overlaps with compute
        {
            const int nx = it + 2;
            if (nx < NCH) {
                const int nst = (st + 2 >= 3) ? st - 1 : st + 2;   // (it+2)%3
                ISSUE_CHUNK(nst, nx * 32);
            }
            CP_COMMIT();
        }

        // ---- compute: 2 k16 steps, ldmatrix-fed ----
#pragma unroll
        for (int ks = 0; ks < 2; ks++) {
            const int kk = ks * 16;

            uint32_t bh[2][4], bl[2][4];
#pragma unroll
            for (int p = 0; p < 2; p++) {
                const int rr = wn + p * 16 + b_r;
                uint32_t off = SWZ_OFF(rr, (kk + b_c) >> 3);
                ldsm_x4(bh[p], bs_hi + off);
                ldsm_x4(bl[p], bs_lo + off);
            }

            uint32_t ah[4][4];
#pragma unroll
            for (int mi = 0; mi < 4; mi++) {
                const int rr = wm + mi * 16 + a_r;
                uint32_t off = SWZ_OFF(rr, (kk + a_c) >> 3);
                ldsm_x4(ah[mi], as_hi + off);
            }
#pragma unroll
            for (int mi = 0; mi < 4; mi++) {
#pragma unroll
                for (int ni = 0; ni < 4; ni++) {
                    mma_bf16(acc[mi][ni], ah[mi], &bh[ni >> 1][(ni & 1) * 2]);
                    mma_bf16(acc[mi][ni], ah[mi], &bl[ni >> 1][(ni & 1) * 2]);
                }
            }
#pragma unroll
            for (int mi = 0; mi < 4; mi++) {
                uint32_t al4[4];
                const int rr = wm + mi * 16 + a_r;
                uint32_t off = SWZ_OFF(rr, (kk + a_c) >> 3);
                ldsm_x4(al4, as_lo + off);
#pragma unroll
                for (int ni = 0; ni < 4; ni++)
                    mma_bf16(acc[mi][ni], al4, &bh[ni >> 1][(ni & 1) * 2]);
            }
        }
        // no trailing sync: next iteration's top sync protects stage reuse
    }
#undef ISSUE_CHUNK

    // ---- epilogue: add bias, write to g_scratch ----
    const float* __restrict__ bp = b1 + (size_t)l * HH;
#pragma unroll
    for (int ni = 0; ni < 4; ni++) {
        int n = n0 + wn + ni * 8 + tg * 2;
        float2 bv = *reinterpret_cast<const float2*>(bp + n);
#pragma unroll
        for (int mi = 0; mi < 4; mi++) {
            int mA = m0 + wm + mi * 16 + g;
            float2 o0, o1;
            o0.x = acc[mi][ni][0] + bv.x;
            o0.y = acc[mi][ni][1] + bv.y;
            o1.x = acc[mi][ni][2] + bv.x;
            o1.y = acc[mi][ni][3] + bv.y;
            *reinterpret_cast<float2*>(g_scratch + (size_t)mA * HH + n) = o0;
            *reinterpret_cast<float2*>(g_scratch + (size_t)(mA + 8) * HH + n) = o1;
        }
    }
}

// ===========================================================================
// Kernel: LN + ReLU + masked pool
// ===========================================================================
__global__ __launch_bounds__(256) void ln_relu_pool_kernel(
    const float* __restrict__ mask,
    const int* __restrict__ lang,
    const float* __restrict__ g1,
    const float* __restrict__ be1)
{
    __shared__ float accum[HH];
    const int blk = blockIdx.x;
    const int b = blk >> 3;
    const int s_base = (blk & 7) * 64;
    const int tid = threadIdx.x;
    const int w = tid >> 5;
    const int lane = tid & 31;

    for (int c = tid; c < HH; c += 256) accum[c] = 0.0f;
    __syncthreads();

    const int l = lang[b];
    const float* __restrict__ g = g1 + (size_t)l * HH;
    const float* __restrict__ be = be1 + (size_t)l * HH;

    float gv[24], bev[24];
#pragma unroll
    for (int i = 0; i < 6; i++) {
        float4 gg = *reinterpret_cast<const float4*>(g + i * 128 + lane * 4);
        float4 bb = *reinterpret_cast<const float4*>(be + i * 128 + lane * 4);
        gv[i * 4 + 0] = gg.x; gv[i * 4 + 1] = gg.y;
        gv[i * 4 + 2] = gg.z; gv[i * 4 + 3] = gg.w;
        bev[i * 4 + 0] = bb.x; bev[i * 4 + 1] = bb.y;
        bev[i * 4 + 2] = bb.z; bev[i * 4 + 3] = bb.w;
    }

    float racc[24];
#pragma unroll
    for (int i = 0; i < 24; i++) racc[i] = 0.0f;

    for (int r = 0; r < 8; r++) {
        const int s = s_base + w * 8 + r;
        const float* __restrict__ row = g_scratch + ((size_t)b * SS + s) * HH;

        float x[24];
        float sum = 0.0f, sq = 0.0f;
#pragma unroll
        for (int i = 0; i < 6; i++) {
            float4 v = *reinterpret_cast<const float4*>(row + i * 128 + lane * 4);
            x[i * 4 + 0] = v.x; x[i * 4 + 1] = v.y;
            x[i * 4 + 2] = v.z; x[i * 4 + 3] = v.w;
            sum += v.x + v.y + v.z + v.w;
            sq += v.x * v.x + v.y * v.y + v.z * v.z + v.w * v.w;
        }
#pragma unroll
        for (int o = 16; o > 0; o >>= 1) {
            sum += __shfl_xor_sync(0xffffffffu, sum, o);
            sq  += __shfl_xor_sync(0xffffffffu, sq, o);
        }
        const float mean = sum * (1.0f / HH);
        const float var = sq * (1.0f / HH) - mean * mean;
        const float rstd = rsqrtf(var + 1e-5f);
        const float mk = mask[b * SS + s];

#pragma unroll
        for (int i = 0; i < 24; i++) {
            float v = (x[i] - mean) * rstd * gv[i] + bev[i];
            racc[i] += fmaxf(v, 0.0f) * mk;
        }
    }

#pragma unroll
    for (int i = 0; i < 6; i++) {
#pragma unroll
        for (int j = 0; j < 4; j++) {
            int c = i * 128 + lane * 4 + j;
            atomicAdd(&accum[c], racc[i * 4 + j]);
        }
    }
    __syncthreads();
    for (int c = tid; c < HH; c += 256)
        atomicAdd(&g_rbar[b * HH + c], accum[c]);
}

// ===========================================================================
// Kernel: gemv2 split-K x8. grid (3, BB, 8). Partial dot into g_comb (atomic).
// ===========================================================================
__global__ __launch_bounds__(256) void gemv2_kernel(
    const int* __restrict__ lang,
    const float* __restrict__ W2)
{
    const int b = blockIdx.y;
    const int z = blockIdx.z;
    const int n = blockIdx.x * 256 + threadIdx.x;
    const int tid = threadIdx.x;
    const int kb = z * 96;
    __shared__ float tvec[96];

    if (tid < 96) tvec[tid] = g_rbar[b * HH + kb + tid];
    __syncthreads();

    const int l = lang[b];
    const float invD = 1.0f / (g_msum[b] + 1e-10f);
    const float* __restrict__ W2l = W2 + (size_t)l * HH * HH + (size_t)kb * HH;

    float acc = 0.0f;
#pragma unroll 8
    for (int h = 0; h < 96; h++)
        acc += tvec[h] * W2l[(size_t)h * HH + n];

    atomicAdd(&g_comb[b * (HH + TT) + n], acc * invD);
}

// ===========================================================================
// Kernel: fuse split-K x7. grid (2, BB, 7). 868 = 7*124.
// ===========================================================================
__global__ __launch_bounds__(256) void fuse_kernel(const float* __restrict__ Wf)
{
    const int b = blockIdx.y;
    const int z = blockIdx.z;
    const int n = blockIdx.x * 256 + threadIdx.x;
    const int tid = threadIdx.x;
    const int ib = z * 124;
    __shared__ float comb[124];

    if (tid < 124) comb[tid] = g_comb[b * (HH + TT) + ib + tid];
    __syncthreads();

    float f = 0.0f;
#pragma unroll 4
    for (int i = 0; i < 124; i++)
        f += comb[i] * Wf[(size_t)(ib + i) * THH + n];

    atomicAdd(&g_fused[b * THH + n], f);
}

// ===========================================================================
// Kernel: final LN + relu. grid BB, block 512.
// ===========================================================================
__global__ __launch_bounds__(512) void final_ln_kernel(
    const float* __restrict__ gf,
    const float* __restrict__ bef,
    float* __restrict__ out)
{
    const int b = blockIdx.x;
    const int tid = threadIdx.x;
    const int lane = tid & 31;
    const int warp = tid >> 5;
    __shared__ float red[32];

    const float f = g_fused[b * THH + tid];

    float sum = f, sq = f * f;
#pragma unroll
    for (int o = 16; o > 0; o >>= 1) {
        sum += __shfl_xor_sync(0xffffffffu, sum, o);
        sq  += __shfl_xor_sync(0xffffffffu, sq, o);
    }
    if (lane == 0) { red[warp] = sum; red[warp + 16] = sq; }
    __syncthreads();
    if (tid < 32) {
        float v = (tid < 16) ? red[tid] : 0.0f;
        float v2 = (tid < 16) ? red[tid + 16] : 0.0f;
#pragma unroll
        for (int o = 8; o > 0; o >>= 1) {
            v  += __shfl_xor_sync(0xffffffffu, v, o);
            v2 += __shfl_xor_sync(0xffffffffu, v2, o);
        }
        if (tid == 0) { red[0] = v; red[1] = v2; }
    }
    __syncthreads();
    const float mean = red[0] * (1.0f / THH);
    const float var = red[1] * (1.0f / THH) - mean * mean;
    const float rstd = rsqrtf(var + 1e-5f);

    float o = (f - mean) * rstd * gf[tid] + bef[tid];
    out[b * THH + tid] = fmaxf(o, 0.0f);
}

// ===========================================================================
extern "C" void kernel_launch(void* const* d_in, const int* in_sizes, int n_in,
                              void* d_out, int out_size)
{
    const float* seq  = (const float*)d_in[0];
    const float* mask = (const float*)d_in[1];
    const int*   lang = (const int*)d_in[2];
    const float* lda  = (const float*)d_in[3];
    const float* W1   = (const float*)d_in[4];
    const float* b1   = (const float*)d_in[5];
    const float* g1   = (const float*)d_in[6];
    const float* be1  = (const float*)d_in[7];
    const float* W2   = (const float*)d_in[8];
    const float* b2   = (const float*)d_in[9];
    const float* Wf   = (const float*)d_in[10];
    const float* bf   = (const float*)d_in[11];
    const float* gf   = (const float*)d_in[12];
    const float* bef  = (const float*)d_in[13];
    float* out = (float*)d_out;

    (void)in_sizes; (void)n_in; (void)out_size;

    cudaFuncSetAttribute(gemm1_mma_kernel,
                         cudaFuncAttributeMaxDynamicSharedMemorySize,
                         NSTAGE * STAGE_BYTES);

    init_kernel<<<BB, 256>>>(mask, lang, b2, lda, bf);
    a_prep_kernel<<<(BB * SS * HH) / 1024, 256>>>(seq);
    w1t_prep_kernel<<<dim3(HH / 32, HH / 32, LL), dim3(32, 8)>>>(W1);
    gemm1_mma_kernel<<<dim3(HH / 128, (BB * SS) / 128), 256,
                      NSTAGE * STAGE_BYTES>>>(lang, b1);
    ln_relu_pool_kernel<<<BB * 8, 256>>>(mask, lang, g1, be1);
    gemv2_kernel<<<dim3(3, BB, 8), 256>>>(lang, W2);
    fuse_kernel<<<dim3(2, BB, 7), 256>>>(Wf);
    final_ln_kernel<<<BB, 512>>>(gf, bef, out);
}

// round 15
// speedup vs baseline: 1.2214x; 1.0219x over previous
#include <cuda_runtime.h>
#include <cuda_bf16.h>
#include <cstdint>

// Problem constants
#define BB 32
#define SS 512
#define HH 768
#define TT 100
#define THH 512
#define LL 5

// Scratch (static device globals — no allocation)
__device__ float g_scratch[BB * SS * HH];   // GEMM1 output: 50.3 MB
__device__ float g_rbar[BB * HH];
__device__ float g_msum[BB];
__device__ float g_comb[BB * (HH + TT)];
__device__ float g_fused[BB * THH];
__device__ __align__(16) __nv_bfloat16 g_w1t_hi[LL * HH * HH];  // W1^T hi, [L][N][K]
__device__ __align__(16) __nv_bfloat16 g_w1t_lo[LL * HH * HH];  // W1^T lo
__device__ __align__(16) __nv_bfloat16 g_a_hi[BB * SS * HH];    // seq hi, [M][K]
__device__ __align__(16) __nv_bfloat16 g_a_lo[BB * SS * HH];    // seq lo

// ---------------------------------------------------------------------------
// mma.sync m16n8k16 bf16 + ldmatrix + cp.async (legacy, base-sm_100-legal)
// ---------------------------------------------------------------------------
__device__ __forceinline__ void mma_bf16(float* c, const uint32_t* a, const uint32_t* b) {
    asm volatile(
        "mma.sync.aligned.m16n8k16.row.col.f32.bf16.bf16.f32 "
        "{%0,%1,%2,%3}, {%4,%5,%6,%7}, {%8,%9}, {%0,%1,%2,%3};"
        : "+f"(c[0]), "+f"(c[1]), "+f"(c[2]), "+f"(c[3])
        : "r"(a[0]), "r"(a[1]), "r"(a[2]), "r"(a[3]), "r"(b[0]), "r"(b[1]));
}
__device__ __forceinline__ void ldsm_x4(uint32_t* r, uint32_t saddr) {
    asm volatile(
        "ldmatrix.sync.aligned.m8n8.x4.shared.b16 {%0,%1,%2,%3}, [%4];"
        : "=r"(r[0]), "=r"(r[1]), "=r"(r[2]), "=r"(r[3]) : "r"(saddr));
}
__device__ __forceinline__ uint32_t smem_u32(const void* p) {
    uint32_t a;
    asm("{ .reg .u64 t; cvta.to.shared.u64 t, %1; cvt.u32.u64 %0, t; }"
        : "=r"(a) : "l"(p));
    return a;
}
__device__ __forceinline__ void cp_async16(uint32_t dst, const void* src) {
    asm volatile("cp.async.cg.shared.global [%0], [%1], 16;"
                 :: "r"(dst), "l"(src));
}
#define CP_COMMIT() asm volatile("cp.async.commit_group;")
#define CP_WAIT1()  asm volatile("cp.async.wait_group 1;")

// Swizzled byte offset within a 128x64B tile: row, chunk c (16B units, 0..3)
#define SWZ_OFF(row, c) ((uint32_t)((row) * 64 + (((c) ^ (((row) >> 1) & 3)) << 4)))

// ===========================================================================
// Kernel: merged prep. Blocks [0, NB_A) = a_prep; [NB_A, NB_A+NB_W) = w1t;
// [NB_A+NB_W, +BB) = init. 256 threads everywhere.
// ===========================================================================
#define NB_A ((BB * SS * HH) / 1024)   // 12288
#define NB_W (24 * 24 * LL)            // 2880

__global__ __launch_bounds__(256) void prep_kernel(
    const float* __restrict__ seq, const float* __restrict__ W1,
    const float* __restrict__ mask, const int* __restrict__ lang,
    const float* __restrict__ b2, const float* __restrict__ lda,
    const float* __restrict__ bf)
{
    const int blk = blockIdx.x;
    const int tid = threadIdx.x;

    if (blk < NB_A) {
        // ---- a_prep: split seq -> bf16 hi/lo, 1 float4/thread ----
        const int i = blk * 256 + tid;
        float4 v = *reinterpret_cast<const float4*>(seq + (size_t)i * 4);
        const float x[4] = {v.x, v.y, v.z, v.w};
        uint32_t h[2], lo[2];
#pragma unroll
        for (int j = 0; j < 2; j++) {
            __nv_bfloat16 h0 = __float2bfloat16(x[2 * j]);
            __nv_bfloat16 h1 = __float2bfloat16(x[2 * j + 1]);
            __nv_bfloat16 l0 = __float2bfloat16(x[2 * j] - __bfloat162float(h0));
            __nv_bfloat16 l1 = __float2bfloat16(x[2 * j + 1] - __bfloat162float(h1));
            h[j]  = ((uint32_t)__bfloat16_as_ushort(h1) << 16) | __bfloat16_as_ushort(h0);
            lo[j] = ((uint32_t)__bfloat16_as_ushort(l1) << 16) | __bfloat16_as_ushort(l0);
        }
        *reinterpret_cast<uint2*>(g_a_hi + (size_t)i * 4) = make_uint2(h[0], h[1]);
        *reinterpret_cast<uint2*>(g_a_lo + (size_t)i * 4) = make_uint2(lo[0], lo[1]);
        return;
    }

    if (blk < NB_A + NB_W) {
        // ---- w1t_prep: W1 -> W1^T split to bf16 hi/lo ----
        __shared__ float tile[32][33];
        const int bi = blk - NB_A;
        const int l = bi / (24 * 24);
        const int rem = bi % (24 * 24);
        const int n0 = (rem % 24) * 32;
        const int k0 = (rem / 24) * 32;
        const int tx = tid & 31;
        const int ty = tid >> 5;
        const float* __restrict__ W = W1 + (size_t)l * HH * HH;
#pragma unroll
        for (int j = 0; j < 4; j++) {
            int k = k0 + ty + j * 8;
            tile[ty + j * 8][tx] = W[(size_t)k * HH + n0 + tx];
        }
        __syncthreads();
#pragma unroll
        for (int j = 0; j < 4; j++) {
            int n = n0 + ty + j * 8;
            float v = tile[tx][ty + j * 8];
            __nv_bfloat16 h = __float2bfloat16(v);
            __nv_bfloat16 lo = __float2bfloat16(v - __bfloat162float(h));
            size_t o = (size_t)l * HH * HH + (size_t)n * HH + k0 + tx;
            g_w1t_hi[o] = h;
            g_w1t_lo[o] = lo;
        }
        return;
    }

    // ---- init: mask sums + seed comb/fused + zero rbar ----
    {
        const int b = blk - NB_A - NB_W;
        const int lane = tid & 31;
        const int warp = tid >> 5;
        __shared__ float red[8];
        __shared__ float sh_m;

        for (int c = tid; c < HH; c += 256) g_rbar[b * HH + c] = 0.0f;

        float ms = 0.0f;
        for (int s = tid; s < SS; s += 256) ms += mask[b * SS + s];
#pragma unroll
        for (int o = 16; o > 0; o >>= 1) ms += __shfl_xor_sync(0xffffffffu, ms, o);
        if (lane == 0) red[warp] = ms;
        __syncthreads();
        if (tid == 0) {
            float v = 0.0f;
#pragma unroll
            for (int i = 0; i < 8; i++) v += red[i];
            g_msum[b] = v;
            sh_m = v;
        }
        __syncthreads();

        const int l = lang[b];
        const float Mtot = sh_m;
        const float invD = 1.0f / (Mtot + 1e-10f);
        for (int n = tid; n < HH; n += 256)
            g_comb[b * (HH + TT) + n] = Mtot * b2[l * HH + n] * invD;
        for (int i = tid; i < TT; i += 256)
            g_comb[b * (HH + TT) + HH + i] = lda[b * TT + i];
        for (int n = tid; n < THH; n += 256)
            g_fused[b * THH + n] = bf[n];
    }
}

// ===========================================================================
// Kernel: GEMM1 via mma.sync bf16-split + ldmatrix + 3-stage cp.async pipeline.
// CTA tile 128x128, BK=32, 8 warps (2m x 4n), warp tile 64x32.
// Swizzled 64B rows -> tile 8KB, stage 32KB, 3 stages = 96KB/CTA, 2 CTA/SM.
// Lo-fragment loads software-pipelined one mi ahead of their MMAs.
// ===========================================================================
#define TILE_BYTES 8192   // 128 * 64
#define STAGE_BYTES 32768
#define NSTAGE 3
#define NCH (HH / 32)     // 24

__global__ void __launch_bounds__(256, 2) gemm1_mma_kernel(
    const int* __restrict__ lang,
    const float* __restrict__ b1)
{
    extern __shared__ char smem[];
    const uint32_t sbase = smem_u32(smem);

    const int tid = threadIdx.x;
    const int wid = tid >> 5;
    const int lane = tid & 31;
    const int g = lane >> 2;
    const int tg = lane & 3;

    const int n0 = blockIdx.x * 128;
    const int m0 = blockIdx.y * 128;
    const int b = m0 / SS;
    const int l = lang[b];

    const int wm = (wid & 1) * 64;
    const int wn = (wid >> 1) * 32;

    // ldmatrix per-lane source coords
    const int a_r = (lane & 7) + 8 * ((lane >> 3) & 1);
    const int a_c = 8 * (lane >> 4);             // elem offset: 0 or 8
    const int b_r = (lane & 7) + 8 * (lane >> 4);
    const int b_c = 8 * ((lane >> 3) & 1);

    const __nv_bfloat16* __restrict__ Ah = g_a_hi + (size_t)m0 * HH;
    const __nv_bfloat16* __restrict__ Al = g_a_lo + (size_t)m0 * HH;
    const __nv_bfloat16* __restrict__ Bh = g_w1t_hi + (size_t)l * HH * HH + (size_t)n0 * HH;
    const __nv_bfloat16* __restrict__ Bl = g_w1t_lo + (size_t)l * HH * HH + (size_t)n0 * HH;

    // cp.async coords: per tile, 512 x 16B chunks; 2 per thread.
    const int ld_row0 = tid >> 2;              // rows 0..63
    const int ld_row1 = 64 + (tid >> 2);       // rows 64..127
    const int ld_ch = tid & 3;                 // 16B chunk index 0..3
    const uint32_t sw_off0 = SWZ_OFF(ld_row0, ld_ch);
    const uint32_t sw_off1 = SWZ_OFF(ld_row1, ld_ch);
    const int ld_e = ld_ch * 8;                // source elem offset

    float acc[4][4][4];
#pragma unroll
    for (int mi = 0; mi < 4; mi++)
#pragma unroll
        for (int ni = 0; ni < 4; ni++)
#pragma unroll
            for (int r = 0; r < 4; r++) acc[mi][ni][r] = 0.0f;

#define ISSUE_CHUNK(ST, K0)                                                     \
    do {                                                                        \
        const uint32_t sb_ = sbase + (ST) * STAGE_BYTES;                        \
        cp_async16(sb_ + 0 * TILE_BYTES + sw_off0,                              \
                   Ah + (size_t)ld_row0 * HH + (K0) + ld_e);                    \
        cp_async16(sb_ + 0 * TILE_BYTES + sw_off1,                              \
                   Ah + (size_t)ld_row1 * HH + (K0) + ld_e);                    \
        cp_async16(sb_ + 1 * TILE_BYTES + sw_off0,                              \
                   Al + (size_t)ld_row0 * HH + (K0) + ld_e);                    \
        cp_async16(sb_ + 1 * TILE_BYTES + sw_off1,                              \
                   Al + (size_t)ld_row1 * HH + (K0) + ld_e);                    \
        cp_async16(sb_ + 2 * TILE_BYTES + sw_off0,                              \
                   Bh + (size_t)ld_row0 * HH + (K0) + ld_e);                    \
        cp_async16(sb_ + 2 * TILE_BYTES + sw_off1,                              \
                   Bh + (size_t)ld_row1 * HH + (K0) + ld_e);                    \
        cp_async16(sb_ + 3 * TILE_BYTES + sw_off0,                              \
                   Bl + (size_t)ld_row0 * HH + (K0) + ld_e);                    \
        cp_async16(sb_ + 3 * TILE_BYTES + sw_off1,                              \
                   Bl + (size_t)ld_row1 * HH + (K0) + ld_e);                    \
    } while (0)

    // ---- prologue: fill stages 0 and 1 ----
    ISSUE_CHUNK(0, 0);
    CP_COMMIT();
    ISSUE_CHUNK(1, 32);
    CP_COMMIT();

    int stage = 0;
    for (int it = 0; it < NCH; ++it) {
        const int st = stage;                  // it % 3
        stage = (stage == 2) ? 0 : stage + 1;
        const uint32_t as_hi = sbase + st * STAGE_BYTES;
        const uint32_t as_lo = as_hi + TILE_BYTES;
        const uint32_t bs_hi = as_hi + 2 * TILE_BYTES;
        const uint32_t bs_lo = as_hi + 3 * TILE_BYTES;

        // chunk it landed when ≤1 newer group remains in flight
        CP_WAIT1();
        __syncthreads();

        // refill the stage freed by iteration it-1; overlaps with compute
        {
            const int nx = it + 2;
            if (nx < NCH) {
                const int nst = (st + 2 >= 3) ? st - 1 : st + 2;   // (it+2)%3
                ISSUE_CHUNK(nst, nx * 32);
            }
            CP_COMMIT();
        }

        // ---- compute: 2 k16 steps, ldmatrix-fed; lo loads pipelined ----
#pragma unroll
        for (int ks = 0; ks < 2; ks++) {
            const int kk = ks * 16;
            const int kc = (kk + a_c) >> 3;    // same for b (a_c/b_c both 0|8)

            uint32_t bh[2][4], bl[2][4];
#pragma unroll
            for (int p = 0; p < 2; p++) {
                const int rr = wn + p * 16 + b_r;
                uint32_t off = SWZ_OFF(rr, (kk + b_c) >> 3);
                ldsm_x4(bh[p], bs_hi + off);
                ldsm_x4(bl[p], bs_lo + off);
            }

            uint32_t ah[4][4];
#pragma unroll
            for (int mi = 0; mi < 4; mi++) {
                uint32_t off = SWZ_OFF(wm + mi * 16 + a_r, kc);
                ldsm_x4(ah[mi], as_hi + off);
            }

            // lo-fragment double buffer: load mi+1 before mi's MMAs
            uint32_t al[2][4];
            ldsm_x4(al[0], as_lo + SWZ_OFF(wm + 0 * 16 + a_r, kc));
#pragma unroll
            for (int mi = 0; mi < 4; mi++) {
                if (mi < 3)
                    ldsm_x4(al[(mi + 1) & 1],
                            as_lo + SWZ_OFF(wm + (mi + 1) * 16 + a_r, kc));
#pragma unroll
                for (int ni = 0; ni < 4; ni++) {
                    mma_bf16(acc[mi][ni], ah[mi], &bh[ni >> 1][(ni & 1) * 2]);
                    mma_bf16(acc[mi][ni], ah[mi], &bl[ni >> 1][(ni & 1) * 2]);
                }
#pragma unroll
                for (int ni = 0; ni < 4; ni++)
                    mma_bf16(acc[mi][ni], al[mi & 1], &bh[ni >> 1][(ni & 1) * 2]);
            }
        }
        // no trailing sync: next iteration's top sync protects stage reuse
    }
#undef ISSUE_CHUNK

    // ---- epilogue: add bias, write to g_scratch ----
    const float* __restrict__ bp = b1 + (size_t)l * HH;
#pragma unroll
    for (int ni = 0; ni < 4; ni++) {
        int n = n0 + wn + ni * 8 + tg * 2;
        float2 bv = *reinterpret_cast<const float2*>(bp + n);
#pragma unroll
        for (int mi = 0; mi < 4; mi++) {
            int mA = m0 + wm + mi * 16 + g;
            float2 o0, o1;
            o0.x = acc[mi][ni][0] + bv.x;
            o0.y = acc[mi][ni][1] + bv.y;
            o1.x = acc[mi][ni][2] + bv.x;
            o1.y = acc[mi][ni][3] + bv.y;
            *reinterpret_cast<float2*>(g_scratch + (size_t)mA * HH + n) = o0;
            *reinterpret_cast<float2*>(g_scratch + (size_t)(mA + 8) * HH + n) = o1;
        }
    }
}

// ===========================================================================
// Kernel: LN + ReLU + masked pool
// ===========================================================================
__global__ __launch_bounds__(256) void ln_relu_pool_kernel(
    const float* __restrict__ mask,
    const int* __restrict__ lang,
    const float* __restrict__ g1,
    const float* __restrict__ be1)
{
    __shared__ float accum[HH];
    const int blk = blockIdx.x;
    const int b = blk >> 3;
    const int s_base = (blk & 7) * 64;
    const int tid = threadIdx.x;
    const int w = tid >> 5;
    const int lane = tid & 31;

    for (int c = tid; c < HH; c += 256) accum[c] = 0.0f;
    __syncthreads();

    const int l = lang[b];
    const float* __restrict__ g = g1 + (size_t)l * HH;
    const float* __restrict__ be = be1 + (size_t)l * HH;

    float gv[24], bev[24];
#pragma unroll
    for (int i = 0; i < 6; i++) {
        float4 gg = *reinterpret_cast<const float4*>(g + i * 128 + lane * 4);
        float4 bb = *reinterpret_cast<const float4*>(be + i * 128 + lane * 4);
        gv[i * 4 + 0] = gg.x; gv[i * 4 + 1] = gg.y;
        gv[i * 4 + 2] = gg.z; gv[i * 4 + 3] = gg.w;
        bev[i * 4 + 0] = bb.x; bev[i * 4 + 1] = bb.y;
        bev[i * 4 + 2] = bb.z; bev[i * 4 + 3] = bb.w;
    }

    float racc[24];
#pragma unroll
    for (int i = 0; i < 24; i++) racc[i] = 0.0f;

    for (int r = 0; r < 8; r++) {
        const int s = s_base + w * 8 + r;
        const float* __restrict__ row = g_scratch + ((size_t)b * SS + s) * HH;

        float x[24];
        float sum = 0.0f, sq = 0.0f;
#pragma unroll
        for (int i = 0; i < 6; i++) {
            float4 v = *reinterpret_cast<const float4*>(row + i * 128 + lane * 4);
            x[i * 4 + 0] = v.x; x[i * 4 + 1] = v.y;
            x[i * 4 + 2] = v.z; x[i * 4 + 3] = v.w;
            sum += v.x + v.y + v.z + v.w;
            sq += v.x * v.x + v.y * v.y + v.z * v.z + v.w * v.w;
        }
#pragma unroll
        for (int o = 16; o > 0; o >>= 1) {
            sum += __shfl_xor_sync(0xffffffffu, sum, o);
            sq  += __shfl_xor_sync(0xffffffffu, sq, o);
        }
        const float mean = sum * (1.0f / HH);
        const float var = sq * (1.0f / HH) - mean * mean;
        const float rstd = rsqrtf(var + 1e-5f);
        const float mk = mask[b * SS + s];

#pragma unroll
        for (int i = 0; i < 24; i++) {
            float v = (x[i] - mean) * rstd * gv[i] + bev[i];
            racc[i] += fmaxf(v, 0.0f) * mk;
        }
    }

#pragma unroll
    for (int i = 0; i < 6; i++) {
#pragma unroll
        for (int j = 0; j < 4; j++) {
            int c = i * 128 + lane * 4 + j;
            atomicAdd(&accum[c], racc[i * 4 + j]);
        }
    }
    __syncthreads();
    for (int c = tid; c < HH; c += 256)
        atomicAdd(&g_rbar[b * HH + c], accum[c]);
}

// ===========================================================================
// Kernel: gemv2 split-K x8. grid (3, BB, 8). Partial dot into g_comb (atomic).
// ===========================================================================
__global__ __launch_bounds__(256) void gemv2_kernel(
    const int* __restrict__ lang,
    const float* __restrict__ W2)
{
    const int b = blockIdx.y;
    const int z = blockIdx.z;
    const int n = blockIdx.x * 256 + threadIdx.x;
    const int tid = threadIdx.x;
    const int kb = z * 96;
    __shared__ float tvec[96];

    if (tid < 96) tvec[tid] = g_rbar[b * HH + kb + tid];
    __syncthreads();

    const int l = lang[b];
    const float invD = 1.0f / (g_msum[b] + 1e-10f);
    const float* __restrict__ W2l = W2 + (size_t)l * HH * HH + (size_t)kb * HH;

    float acc = 0.0f;
#pragma unroll 8
    for (int h = 0; h < 96; h++)
        acc += tvec[h] * W2l[(size_t)h * HH + n];

    atomicAdd(&g_comb[b * (HH + TT) + n], acc * invD);
}

// ===========================================================================
// Kernel: fuse split-K x7. grid (2, BB, 7). 868 = 7*124.
// ===========================================================================
__global__ __launch_bounds__(256) void fuse_kernel(const float* __restrict__ Wf)
{
    const int b = blockIdx.y;
    const int z = blockIdx.z;
    const int n = blockIdx.x * 256 + threadIdx.x;
    const int tid = threadIdx.x;
    const int ib = z * 124;
    __shared__ float comb[124];

    if (tid < 124) comb[tid] = g_comb[b * (HH + TT) + ib + tid];
    __syncthreads();

    float f = 0.0f;
#pragma unroll 4
    for (int i = 0; i < 124; i++)
        f += comb[i] * Wf[(size_t)(ib + i) * THH + n];

    atomicAdd(&g_fused[b * THH + n], f);
}

// ===========================================================================
// Kernel: final LN + relu. grid BB, block 512.
// ===========================================================================
__global__ __launch_bounds__(512) void final_ln_kernel(
    const float* __restrict__ gf,
    const float* __restrict__ bef,
    float* __restrict__ out)
{
    const int b = blockIdx.x;
    const int tid = threadIdx.x;
    const int lane = tid & 31;
    const int warp = tid >> 5;
    __shared__ float red[32];

    const float f = g_fused[b * THH + tid];

    float sum = f, sq = f * f;
#pragma unroll
    for (int o = 16; o > 0; o >>= 1) {
        sum += __shfl_xor_sync(0xffffffffu, sum, o);
        sq  += __shfl_xor_sync(0xffffffffu, sq, o);
    }
    if (lane == 0) { red[warp] = sum; red[warp + 16] = sq; }
    __syncthreads();
    if (tid < 32) {
        float v = (tid < 16) ? red[tid] : 0.0f;
        float v2 = (tid < 16) ? red[tid + 16] : 0.0f;
#pragma unroll
        for (int o = 8; o > 0; o >>= 1) {
            v  += __shfl_xor_sync(0xffffffffu, v, o);
            v2 += __shfl_xor_sync(0xffffffffu, v2, o);
        }
        if (tid == 0) { red[0] = v; red[1] = v2; }
    }
    __syncthreads();
    const float mean = red[0] * (1.0f / THH);
    const float var = red[1] * (1.0f / THH) - mean * mean;
    const float rstd = rsqrtf(var + 1e-5f);

    float o = (f - mean) * rstd * gf[tid] + bef[tid];
    out[b * THH + tid] = fmaxf(o, 0.0f);
}

// ===========================================================================
extern "C" void kernel_launch(void* const* d_in, const int* in_sizes, int n_in,
                              void* d_out, int out_size)
{
    const float* seq  = (const float*)d_in[0];
    const float* mask = (const float*)d_in[1];
    const int*   lang = (const int*)d_in[2];
    const float* lda  = (const float*)d_in[3];
    const float* W1   = (const float*)d_in[4];
    const float* b1   = (const float*)d_in[5];
    const float* g1   = (const float*)d_in[6];
    const float* be1  = (const float*)d_in[7];
    const float* W2   = (const float*)d_in[8];
    const float* b2   = (const float*)d_in[9];
    const float* Wf   = (const float*)d_in[10];
    const float* bf   = (const float*)d_in[11];
    const float* gf   = (const float*)d_in[12];
    const float* bef  = (const float*)d_in[13];
    float* out = (float*)d_out;

    (void)in_sizes; (void)n_in; (void)out_size;

    cudaFuncSetAttribute(gemm1_mma_kernel,
                         cudaFuncAttributeMaxDynamicSharedMemorySize,
                         NSTAGE * STAGE_BYTES);

    prep_kernel<<<NB_A + NB_W + BB, 256>>>(seq, W1, mask, lang, b2, lda, bf);
    gemm1_mma_kernel<<<dim3(HH / 128, (BB * SS) / 128), 256,
                      NSTAGE * STAGE_BYTES>>>(lang, b1);
    ln_relu_pool_kernel<<<BB * 8, 256>>>(mask, lang, g1, be1);
    gemv2_kernel<<<dim3(3, BB, 8), 256>>>(lang, W2);
    fuse_kernel<<<dim3(2, BB, 7), 256>>>(Wf);
    final_ln_kernel<<<BB, 512>>>(gf, bef, out);
}